// round 5
// baseline (speedup 1.0000x reference)
#include <cuda_runtime.h>
#include <math.h>

// Problem constants (SUBDIVISIONS=7, BATCH=16)
#define BATCH    16
#define NV       163842        // total vertices (grid + 2 poles)
#define YXN      163840        // grid vertices (Y=640, X=256)
#define XDIM     256
#define NFACE    327680
#define NDIR     983040        // directed edges == 3*NFACE == sum(deg)
#define VPB      32            // vertices per block (512-thread blocks)

// Scratch (__device__ globals; no runtime allocation)
__device__ float    g_x[(size_t)NV * BATCH];  // positions, [vertex][batch], planes
__device__ float    g_y[(size_t)NV * BATCH];
__device__ float    g_z[(size_t)NV * BATCH];
__device__ int      g_off[NV + 1];            // CSR offsets (edge-degree == face-degree)
__device__ int      g_cursor[NV];
__device__ int2     g_pairs[NDIR];            // per vertex slot: opposite edge (p,q) in winding order
__device__ double   g_acc;
__device__ unsigned g_done;

// ---------------------------------------------------------------------------
// K1: CSR offsets from sorted edge_src; zero cursors / accumulator / counter
// ---------------------------------------------------------------------------
__global__ void __launch_bounds__(512) k_prep(const int* __restrict__ esrc) {
    int t = blockIdx.x * blockDim.x + threadIdx.x;
    if (t < NDIR) {
        int s = __ldg(&esrc[t]);
        if (t == 0) g_off[s] = 0;
        else if (__ldg(&esrc[t - 1]) != s) g_off[s] = t;
    }
    if (t < NV) g_cursor[t] = 0;
    if (t == 0) { g_acc = 0.0; g_done = 0u; g_off[NV] = NDIR; }
}

// ---------------------------------------------------------------------------
// K2: build transposed position planes g_{x,y,z}[vertex][batch].
// Block = 32 vertices x 16 batches; poles fused into block 0.
// ---------------------------------------------------------------------------
__global__ void __launch_bounds__(512) k_build(const float* __restrict__ inp) {
    __shared__ float st[3][VPB][BATCH + 1];
    int tid = threadIdx.x;
    int i0  = blockIdx.x * VPB;
    // Stage: full 128B lines (32 consecutive floats per warp, fixed (b,c))
    {
        int lo = tid & 31;          // vertex offset
        int hv = tid >> 5;          // batch
        size_t base = (size_t)hv * 3 * YXN + (size_t)(i0 + lo);
#pragma unroll
        for (int c = 0; c < 3; c++)
            st[c][lo][hv] = __ldg(&inp[base + (size_t)c * YXN]);
    }
    __syncthreads();
    // Write planes: tid order == (vertex,batch) linear -> 2KB coalesced/component
    {
        int hv2 = tid >> 4;         // local vertex
        int lo2 = tid & 15;         // batch
        size_t o = (size_t)(i0 + hv2) * BATCH + lo2;
        g_x[o] = st[0][hv2][lo2];
        g_y[o] = st[1][hv2][lo2];
        g_z[o] = st[2][hv2][lo2];
    }
    // Poles: 2 poles x 16 batches by block 0's first warp
    if (blockIdx.x == 0 && tid < 32) {
        int b    = tid & 15;
        int pole = tid >> 4;
        const float* base = inp + (size_t)b * 3 * YXN;
        float sx = 0.f, sy = 0.f, sz = 0.f;
#pragma unroll
        for (int r = 0; r < 5; r++) {
            int idx = pole ? ((r * 128 + 127) * XDIM + (XDIM - 1))
                           : (r * 128 * XDIM);
            sx += __ldg(&base[idx]);
            sy += __ldg(&base[YXN + idx]);
            sz += __ldg(&base[2 * YXN + idx]);
        }
        size_t o = (size_t)(YXN + pole) * BATCH + b;
        g_x[o] = sx * 0.2f; g_y[o] = sy * 0.2f; g_z[o] = sz * 0.2f;
    }
}

// ---------------------------------------------------------------------------
// K3: per face (a,b,c), deposit opposite edge in winding order at each corner
// ---------------------------------------------------------------------------
__global__ void k_pairs(const int* __restrict__ faces) {
    int f = blockIdx.x * blockDim.x + threadIdx.x;
    if (f >= NFACE) return;
    int a = __ldg(&faces[3 * f]);
    int b = __ldg(&faces[3 * f + 1]);
    int c = __ldg(&faces[3 * f + 2]);
    int pa = atomicAdd(&g_cursor[a], 1); g_pairs[g_off[a] + pa] = make_int2(b, c);
    int pb = atomicAdd(&g_cursor[b], 1); g_pairs[g_off[b] + pb] = make_int2(c, a);
    int pc = atomicAdd(&g_cursor[c], 1); g_pairs[g_off[c] + pc] = make_int2(a, b);
}

// ---------------------------------------------------------------------------
// K4: fused loss + in-register ring chaining + last-block finalize.
// Block = 32 vertices x 16 batches; half-warp = one vertex.
// vn_i = sum of cross(v_t, v_{t+1}) over the ordered ring (exact identity
// with the reference's per-face cross(v1-v0, v2-v0) fan sum).
// ---------------------------------------------------------------------------
__global__ void __launch_bounds__(512)
k_main(const float* __restrict__ target, float* __restrict__ out) {
    __shared__ float st[9][VPB][BATCH + 1];
    int tid = threadIdx.x;
    int i0  = blockIdx.x * VPB;

    // Stage target tile: full 128B lines per (c, batch) row
    {
        int lo = tid & 31;          // vertex offset
        int hv = tid >> 5;          // batch
        int gi = i0 + lo;
        size_t base = (size_t)hv * 9 * NV + (size_t)gi;
#pragma unroll
        for (int c = 0; c < 9; c++)
            st[c][lo][hv] = (gi < NV) ? __ldg(&target[base + (size_t)c * NV]) : 0.f;
    }
    __syncthreads();

    int hv2 = tid >> 4;             // local vertex (0..31)
    int b   = tid & 15;             // batch
    int i   = i0 + hv2;
    float contrib = 0.f;

    if (i < NV) {
        int s   = __ldg(&g_off[i]);
        int cnt = __ldg(&g_off[i + 1]) - s;    // 5 or 6 (uniform per half-warp)

        // In-register ring chaining from (p,q) pairs (broadcast 8B loads,
        // redundant across the 16 lanes of the half-warp — ALU is idle anyway).
        int p[6], q[6];
#pragma unroll
        for (int k = 0; k < 6; k++) {
            int2 pr = (k < cnt) ? __ldg(&g_pairs[s + k]) : make_int2(0x7fffffff, 0x7fffffff);
            p[k] = pr.x; q[k] = pr.y;
        }
        int idx[6];
        int cur = 0x7fffffff, nxt = 0;
#pragma unroll
        for (int k = 0; k < 6; k++) if (p[k] < cur) { cur = p[k]; nxt = q[k]; }
        idx[0] = cur;
        cur = nxt;
#pragma unroll
        for (int t = 1; t < 6; t++) {
            if (t < cnt) {
                idx[t] = cur;
                int nq = cur;
#pragma unroll
                for (int k = 0; k < 6; k++) if (p[k] == cur) nq = q[k];
                cur = nq;
            } else idx[t] = idx[0];
        }

        size_t oi = (size_t)i * BATCH + b;
        float vix = g_x[oi], viy = g_y[oi], viz = g_z[oi];

        // Gather neighbor positions: 64B contiguous per plane per half-warp
        float nbx[6], nby[6], nbz[6];
#pragma unroll
        for (int t = 0; t < 6; t++) {
            size_t o = (size_t)idx[t] * BATCH + b;
            nbx[t] = g_x[o]; nby[t] = g_y[o]; nbz[t] = g_z[o];
        }

        // Laplacian neighbor sum
        float nx = 0.f, ny = 0.f, nz = 0.f;
#pragma unroll
        for (int t = 0; t < 6; t++)
            if (t < cnt) { nx += nbx[t]; ny += nby[t]; nz += nbz[t]; }

        // Vertex normal via ring cross sum (+ wrap)
        float vnx = 0.f, vny = 0.f, vnz = 0.f;
#pragma unroll
        for (int t = 0; t < 5; t++) {
            if (t + 1 < cnt) {
                vnx += nby[t] * nbz[t + 1] - nbz[t] * nby[t + 1];
                vny += nbz[t] * nbx[t + 1] - nbx[t] * nbz[t + 1];
                vnz += nbx[t] * nby[t + 1] - nby[t] * nbx[t + 1];
            }
        }
        int lastt = cnt - 1;
        vnx += nby[lastt] * nbz[0] - nbz[lastt] * nby[0];
        vny += nbz[lastt] * nbx[0] - nbx[lastt] * nbz[0];
        vnz += nbx[lastt] * nby[0] - nby[lastt] * nbx[0];

        float idg = 1.0f / (float)cnt;
        float lx = vix - nx * idg;
        float ly = viy - ny * idg;
        float lz = viz - nz * idg;

        float tvx = st[0][hv2][b], tvy = st[1][hv2][b], tvz = st[2][hv2][b];
        float tnx = st[3][hv2][b], tny = st[4][hv2][b], tnz = st[5][hv2][b];
        float tlx = st[6][hv2][b], tly = st[7][hv2][b], tlz = st[8][hv2][b];

        float dpx = vix - tvx, dpy = viy - tvy, dpz = viz - tvz;
        float pos_sse = dpx * dpx + dpy * dpy + dpz * dpz;

        float dlx = lx - tlx, dly = ly - tly, dlz = lz - tlz;
        float lap_sse = dlx * dlx + dly * dly + dlz * dlz;

        // cosine, replicating the reference's epsilon chain
        float nrm   = sqrtf(vnx * vnx + vny * vny + vnz * vnz);
        float inv_n = 1.0f / fmaxf(nrm, 1e-12f);
        float hx = vnx * inv_n, hy = vny * inv_n, hz = vnz * inv_n;
        float hn  = sqrtf(hx * hx + hy * hy + hz * hz);
        float tnn = sqrtf(tnx * tnx + tny * tny + tnz * tnz);
        float cosv = (hx * tnx + hy * tny + hz * tnz) / fmaxf(hn * tnn, 1e-8f);

        const float invP = 1.0f / ((float)BATCH * (float)NV * 3.0f);
        const float invN = 1.0f / ((float)BATCH * (float)NV);
        contrib = (pos_sse + lap_sse) * invP + (1.0f - cosv) * invN;
    }

    // Block reduce -> one double atomic per block
#pragma unroll
    for (int o = 16; o > 0; o >>= 1)
        contrib += __shfl_down_sync(0xffffffff, contrib, o);

    __shared__ float ws[16];
    int lane = threadIdx.x & 31;
    int w    = threadIdx.x >> 5;
    if (lane == 0) ws[w] = contrib;
    __syncthreads();
    if (w == 0) {
        float v = (lane < 16) ? ws[lane] : 0.f;
#pragma unroll
        for (int o = 8; o > 0; o >>= 1)
            v += __shfl_down_sync(0xffff, v, o);
        if (lane == 0) {
            atomicAdd(&g_acc, (double)v);
            __threadfence();
            unsigned done = atomicAdd(&g_done, 1u);
            if (done == gridDim.x - 1) {
                __threadfence();
                out[0] = (float)g_acc;
            }
        }
    }
}

// ---------------------------------------------------------------------------
// inputs order: inputs, target, ico_faces, edge_src, edge_dst, degree
// ---------------------------------------------------------------------------
extern "C" void kernel_launch(void* const* d_in, const int* in_sizes, int n_in,
                              void* d_out, int out_size) {
    const float* inputs = (const float*)d_in[0];
    const float* target = (const float*)d_in[1];
    const int*   faces  = (const int*)  d_in[2];
    const int*   esrc   = (const int*)  d_in[3];

    k_prep <<<(NDIR + 511) / 512, 512>>>(esrc);
    k_build<<<YXN / VPB, 512>>>(inputs);
    k_pairs<<<(NFACE + 255) / 256, 256>>>(faces);
    k_main <<<(NV + VPB - 1) / VPB, 512>>>(target, (float*)d_out);
}